// round 14
// baseline (speedup 1.0000x reference)
#include <cuda_runtime.h>
#include <cuda_bf16.h>
#include <cstdint>

#define T_TOK   8192
#define H_DIM   2048
#define I_DIM   4096
#define NE      8
#define LISTCAP 16384
#define MAXT    96
#define HM_ROWS 18432

#define STG     24576          /* stage: Ah(8K)|Al(8K)|Bh(4K)|Bl(4K) */
#define P_AL    8192
#define P_BH    16384
#define P_BL    20480
#define SMEM_DYN (3 * STG)

// ---------------- device scratch (no allocations allowed) ----------------
__device__ int   g_cnt[NE];
__device__ int   g_base[NE];
__device__ int   g_ntiles;
__device__ int   g_tile_e[MAXT];
__device__ int   g_tile_m[MAXT];
__device__ int   g_tok[NE * LISTCAP];
__device__ float g_coef[NE * LISTCAP];

__device__ __nv_bfloat16 g_xh[(size_t)T_TOK * H_DIM];
__device__ __nv_bfloat16 g_xl[(size_t)T_TOK * H_DIM];
__device__ __nv_bfloat16 g_w13h[(size_t)NE * 2 * I_DIM * H_DIM];   // permuted gate/up
__device__ __nv_bfloat16 g_w13l[(size_t)NE * 2 * I_DIM * H_DIM];
__device__ __nv_bfloat16 g_w2h[(size_t)NE * H_DIM * I_DIM];
__device__ __nv_bfloat16 g_w2l[(size_t)NE * H_DIM * I_DIM];
__device__ __nv_bfloat16 g_hmh[(size_t)HM_ROWS * I_DIM];
__device__ __nv_bfloat16 g_hml[(size_t)HM_ROWS * I_DIM];

// ---------------- helpers ----------------
__device__ __forceinline__ uint32_t smem_u32(const void* p) {
    uint32_t a;
    asm("{ .reg .u64 t; cvta.to.shared.u64 t, %1; cvt.u32.u64 %0, t; }" : "=r"(a) : "l"(p));
    return a;
}

// swizzled offset in a [rows][32B] plane: 16B chunk XOR'd with row bit2
#define SWZ16(r, c) ((uint32_t)((r) * 32 + ((((c) ^ (((r) >> 2) & 1))) << 4)))

#define CP16(dst, src) \
    asm volatile("cp.async.cg.shared.global [%0], [%1], 16;" :: "r"(dst), "l"(src))
#define CP_COMMIT() asm volatile("cp.async.commit_group;" ::: "memory")
#define CP_WAIT1()  asm volatile("cp.async.wait_group 1;" ::: "memory")
#define CP_WAIT0()  asm volatile("cp.async.wait_group 0;" ::: "memory")

__device__ __forceinline__ void ldsm4(uint32_t* r, uint32_t addr) {
    asm volatile("ldmatrix.sync.aligned.m8n8.x4.shared.b16 {%0,%1,%2,%3}, [%4];"
                 : "=r"(r[0]), "=r"(r[1]), "=r"(r[2]), "=r"(r[3]) : "r"(addr));
}

__device__ __forceinline__ void mma_bf16(float* c, const uint32_t* a,
                                         uint32_t b0, uint32_t b1) {
    asm volatile(
        "mma.sync.aligned.m16n8k16.row.col.f32.bf16.bf16.f32 "
        "{%0,%1,%2,%3}, {%4,%5,%6,%7}, {%8,%9}, {%0,%1,%2,%3};\n"
        : "+f"(c[0]), "+f"(c[1]), "+f"(c[2]), "+f"(c[3])
        : "r"(a[0]), "r"(a[1]), "r"(a[2]), "r"(a[3]), "r"(b0), "r"(b1));
}

__device__ __forceinline__ void split4(float4 v, uint2& hu, uint2& lu) {
    __nv_bfloat162 a, b, c, d;
    a.x = __float2bfloat16(v.x);
    a.y = __float2bfloat16(v.y);
    b.x = __float2bfloat16(v.z);
    b.y = __float2bfloat16(v.w);
    c.x = __float2bfloat16(v.x - __bfloat162float(a.x));
    c.y = __float2bfloat16(v.y - __bfloat162float(a.y));
    d.x = __float2bfloat16(v.z - __bfloat162float(b.x));
    d.y = __float2bfloat16(v.w - __bfloat162float(b.y));
    hu.x = *reinterpret_cast<unsigned*>(&a);
    hu.y = *reinterpret_cast<unsigned*>(&b);
    lu.x = *reinterpret_cast<unsigned*>(&c);
    lu.y = *reinterpret_cast<unsigned*>(&d);
}

__device__ __forceinline__ void srow(const float* __restrict__ src, int n4, int lane,
                                     __nv_bfloat16* dh, __nv_bfloat16* dl) {
    const float4* s4 = (const float4*)src;
    uint2* dh2 = (uint2*)dh;
    uint2* dl2 = (uint2*)dl;
    for (int i = lane; i < n4; i += 32) {
        uint2 hu, lu;
        split4(s4[i], hu, lu);
        dh2[i] = hu;
        dl2[i] = lu;
    }
}

// ---------------- small kernels ----------------
__global__ void k_clear(float* __restrict__ out, int n) {
    int i = blockIdx.x * 256 + threadIdx.x;
    if (i < n) out[i] = 0.0f;
}

__global__ void k_route(const int* __restrict__ rt, const float* __restrict__ rw) {
    __shared__ int scnt[NE], scur[NE];
    int tid = threadIdx.x;
    if (tid < NE) scnt[tid] = 0;
    __syncthreads();
    for (int t = tid; t < T_TOK; t += 256) {
        atomicAdd(&scnt[rt[2 * t]], 1);
        atomicAdd(&scnt[rt[2 * t + 1]], 1);
    }
    __syncthreads();
    if (tid == 0) {
        int base = 0, nt = 0;
        for (int e = 0; e < NE; ++e) {
            int c = scnt[e];
            g_cnt[e] = c;
            g_base[e] = base;
            for (int m0 = 0; m0 < c && nt < MAXT; m0 += 256) {
                g_tile_e[nt] = e;
                g_tile_m[nt] = m0;
                nt++;
            }
            base += (c + 255) / 256 * 256;
        }
        g_ntiles = nt;
    }
    if (tid < NE) scur[tid] = 0;
    __syncthreads();
    for (int t = tid; t < T_TOK; t += 256) {
#pragma unroll
        for (int k = 0; k < 2; ++k) {
            int e = rt[2 * t + k];
            int p = atomicAdd(&scur[e], 1);
            g_tok[e * LISTCAP + p]  = t;
            g_coef[e * LISTCAP + p] = rw[2 * t + k];
        }
    }
}

// splits X ([0,1024) blocks), permuted W13 ([1024,9216)), W2 ([9216,11264))
__global__ void k_splitall(const float* __restrict__ x, const float* __restrict__ w13,
                           const float* __restrict__ w2) {
    int wrow = blockIdx.x * 8 + (threadIdx.x >> 5);
    int lane = threadIdx.x & 31;
    if (blockIdx.x < 1024) {
        int row = wrow;
        srow(x + (size_t)row * H_DIM, H_DIM / 4, lane,
             g_xh + (size_t)row * H_DIM, g_xl + (size_t)row * H_DIM);
    } else if (blockIdx.x < 9216) {
        int row = wrow - 8192;
        int e = row >> 13, n = row & 8191;
        int j = n >> 1;
        int srcrow = (n & 1) ? (I_DIM + j) : j;
        srow(w13 + ((size_t)e * 2 * I_DIM + srcrow) * H_DIM, H_DIM / 4, lane,
             g_w13h + (size_t)row * H_DIM, g_w13l + (size_t)row * H_DIM);
    } else {
        int row = wrow - 73728;
        srow(w2 + (size_t)row * I_DIM, I_DIM / 4, lane,
             g_w2h + (size_t)row * I_DIM, g_w2l + (size_t)row * I_DIM);
    }
}

// ---------------- bf16 3-term fragment core (one K=16 stage) ----------------
// 8 warps: wm = wid&3 (64 rows of 256), wn = wid>>2 (64 cols of 128)
__device__ __forceinline__ void compute_stage(uint32_t st, int wm, int wn, int lane,
                                              float (&acc)[4][8][4]) {
    const int rsel = lane & 15;
    const int csel = lane >> 4;
    uint32_t bh[4][4], bl[4][4];
#pragma unroll
    for (int p = 0; p < 4; ++p) {
        uint32_t b = st + P_BH + SWZ16(wn * 64 + p * 16 + rsel, csel);
        ldsm4(bh[p], b);
        ldsm4(bl[p], b + (P_BL - P_BH));
    }
#pragma unroll
    for (int mf = 0; mf < 4; ++mf) {
        uint32_t ah[4], al[4];
        uint32_t a = st + SWZ16(wm * 64 + mf * 16 + rsel, csel);
        ldsm4(ah, a);
        ldsm4(al, a + P_AL);
#pragma unroll
        for (int p = 0; p < 4; ++p)
#pragma unroll
            for (int s = 0; s < 2; ++s) {
                int nf = p * 2 + s;
                mma_bf16(acc[mf][nf], ah, bh[p][s], bh[p][s + 2]);
                mma_bf16(acc[mf][nf], ah, bl[p][s], bl[p][s + 2]);
                mma_bf16(acc[mf][nf], al, bh[p][s], bh[p][s + 2]);
            }
    }
}

// ---------------- GEMM1: Xs[gathered 256] @ W13s^T[128], SwiGLU -> split Hm ------
__global__ __launch_bounds__(256, 1) void k_gemm1() {
    extern __shared__ __align__(128) char smem[];

    const int tid = threadIdx.x, lane = tid & 31, wid = tid >> 5;
    const int wm = wid & 3, wn = wid >> 2;

    const int tile = blockIdx.y;
    if (tile >= g_ntiles) return;
    const int e   = g_tile_e[tile];
    const int m0  = g_tile_m[tile];
    const int n0  = blockIdx.x * 128;          // over 8192 permuted rows
    const int cnt = g_cnt[e];
    const int* tokp = g_tok + e * LISTCAP;

    // cp.async: thread t -> A rows r0, r0+128 (hi+lo) and B row r0 (hi+lo), chunk ct
    const int r0 = tid >> 1, ct = tid & 1;
    int tok0 = (m0 + r0 < cnt) ? tokp[m0 + r0] : tokp[0];
    int tok1 = (m0 + 128 + r0 < cnt) ? tokp[m0 + 128 + r0] : tokp[0];
    const __nv_bfloat16* a0h = g_xh + (size_t)tok0 * H_DIM + ct * 8;
    const __nv_bfloat16* a1h = g_xh + (size_t)tok1 * H_DIM + ct * 8;
    const __nv_bfloat16* a0l = g_xl + (size_t)tok0 * H_DIM + ct * 8;
    const __nv_bfloat16* a1l = g_xl + (size_t)tok1 * H_DIM + ct * 8;
    const size_t brow = ((size_t)e * 2 * I_DIM + n0 + r0) * H_DIM + ct * 8;
    const __nv_bfloat16* b0h = g_w13h + brow;
    const __nv_bfloat16* b0l = g_w13l + brow;

    const uint32_t sb = smem_u32(smem);
    const uint32_t dA0 = SWZ16(r0, ct);
    const uint32_t dA1 = SWZ16(128 + r0, ct);
    const uint32_t dB  = P_BH + SWZ16(r0, ct);

#define G_ISSUE(it)                                                          \
    do {                                                                     \
        uint32_t b_ = sb + ((it) % 3) * STG;                                 \
        int o_ = (it) * 16;                                                  \
        CP16(b_ + dA0, a0h + o_);                                            \
        CP16(b_ + dA1, a1h + o_);                                            \
        CP16(b_ + P_AL + dA0, a0l + o_);                                     \
        CP16(b_ + P_AL + dA1, a1l + o_);                                     \
        CP16(b_ + dB, b0h + o_);                                             \
        CP16(b_ + dB + 4096, b0l + o_);                                      \
        CP_COMMIT();                                                         \
    } while (0)

    float acc[4][8][4];
#pragma unroll
    for (int a = 0; a < 4; ++a)
#pragma unroll
        for (int b = 0; b < 8; ++b)
#pragma unroll
            for (int d = 0; d < 4; ++d) acc[a][b][d] = 0.0f;

    const int KT = H_DIM / 16;   // 128
    G_ISSUE(0);
    G_ISSUE(1);
#pragma unroll 1
    for (int it = 0; it < KT; ++it) {
        if (it < KT - 1) CP_WAIT1(); else CP_WAIT0();
        __syncthreads();
        if (it + 2 < KT) G_ISSUE(it + 2);
        compute_stage(sb + (it % 3) * STG, wm, wn, lane, acc);
    }

    // epilogue: SwiGLU -> split bf16 Hm (gate even / up odd interleave)
    const int gq = lane >> 2, t4 = lane & 3;
    const int rowbase = g_base[e] + m0 + wm * 64;
#pragma unroll
    for (int mf = 0; mf < 4; ++mf) {
#pragma unroll
        for (int nf = 0; nf < 8; ++nf) {
            int j = ((n0 + wn * 64 + nf * 8) >> 1) + t4;
#pragma unroll
            for (int hh = 0; hh < 2; ++hh) {
                float g = acc[mf][nf][2 * hh];
                float u = acc[mf][nf][2 * hh + 1];
                float hv = u * g / (1.0f + __expf(-g));
                int row = rowbase + mf * 16 + gq + 8 * hh;
                __nv_bfloat16 hi = __float2bfloat16(hv);
                __nv_bfloat16 lo = __float2bfloat16(hv - __bfloat162float(hi));
                g_hmh[(size_t)row * I_DIM + j] = hi;
                g_hml[(size_t)row * I_DIM + j] = lo;
            }
        }
    }
#undef G_ISSUE
}

// ---------------- GEMM2: Hms[256] @ W2s^T[128], coef atomic scatter -> out ------
__global__ __launch_bounds__(256, 1) void k_gemm2(float* __restrict__ out) {
    extern __shared__ __align__(128) char smem[];

    const int tid = threadIdx.x, lane = tid & 31, wid = tid >> 5;
    const int wm = wid & 3, wn = wid >> 2;

    const int tile = blockIdx.y;
    if (tile >= g_ntiles) return;
    const int e   = g_tile_e[tile];
    const int m0  = g_tile_m[tile];
    const int n0  = blockIdx.x * 128;          // over H_DIM
    const int cnt = g_cnt[e];
    const int rb  = g_base[e];

    const int r0 = tid >> 1, ct = tid & 1;
    const size_t ar0 = (size_t)(rb + m0 + r0) * I_DIM + ct * 8;
    const size_t ar1 = (size_t)(rb + m0 + 128 + r0) * I_DIM + ct * 8;
    const __nv_bfloat16* a0h = g_hmh + ar0;
    const __nv_bfloat16* a1h = g_hmh + ar1;
    const __nv_bfloat16* a0l = g_hml + ar0;
    const __nv_bfloat16* a1l = g_hml + ar1;
    const size_t brow = ((size_t)e * H_DIM + n0 + r0) * I_DIM + ct * 8;
    const __nv_bfloat16* b0h = g_w2h + brow;
    const __nv_bfloat16* b0l = g_w2l + brow;

    const uint32_t sb = smem_u32(smem);
    const uint32_t dA0 = SWZ16(r0, ct);
    const uint32_t dA1 = SWZ16(128 + r0, ct);
    const uint32_t dB  = P_BH + SWZ16(r0, ct);

#define G_ISSUE(it)                                                          \
    do {                                                                     \
        uint32_t b_ = sb + ((it) % 3) * STG;                                 \
        int o_ = (it) * 16;                                                  \
        CP16(b_ + dA0, a0h + o_);                                            \
        CP16(b_ + dA1, a1h + o_);                                            \
        CP16(b_ + P_AL + dA0, a0l + o_);                                     \
        CP16(b_ + P_AL + dA1, a1l + o_);                                     \
        CP16(b_ + dB, b0h + o_);                                             \
        CP16(b_ + dB + 4096, b0l + o_);                                      \
        CP_COMMIT();                                                         \
    } while (0)

    float acc[4][8][4];
#pragma unroll
    for (int a = 0; a < 4; ++a)
#pragma unroll
        for (int b = 0; b < 8; ++b)
#pragma unroll
            for (int d = 0; d < 4; ++d) acc[a][b][d] = 0.0f;

    const int KT = I_DIM / 16;   // 256
    G_ISSUE(0);
    G_ISSUE(1);
#pragma unroll 1
    for (int it = 0; it < KT; ++it) {
        if (it < KT - 1) CP_WAIT1(); else CP_WAIT0();
        __syncthreads();
        if (it + 2 < KT) G_ISSUE(it + 2);
        compute_stage(sb + (it % 3) * STG, wm, wn, lane, acc);
    }

    // epilogue: coef-scaled scatter (exactly 2 commutative fp32 adds / element)
    const int gq = lane >> 2, t4 = lane & 3;
    const int* tokp = g_tok + e * LISTCAP;
    const float* cfp = g_coef + e * LISTCAP;
#pragma unroll
    for (int mf = 0; mf < 4; ++mf) {
#pragma unroll
        for (int hh = 0; hh < 2; ++hh) {
            int mm = m0 + wm * 64 + mf * 16 + gq + 8 * hh;
            if (mm < cnt) {
                int tok  = tokp[mm];
                float cf = cfp[mm];
                float* orow = out + (size_t)tok * H_DIM;
#pragma unroll
                for (int nf = 0; nf < 8; ++nf) {
                    int col = n0 + wn * 64 + nf * 8 + 2 * t4;
                    atomicAdd(&orow[col],     cf * acc[mf][nf][2 * hh]);
                    atomicAdd(&orow[col + 1], cf * acc[mf][nf][2 * hh + 1]);
                }
            }
        }
    }
#undef G_ISSUE
}

// --------------------------------------------------------------------------
extern "C" void kernel_launch(void* const* d_in, const int* in_sizes, int n_in,
                              void* d_out, int out_size) {
    const float* x   = (const float*)d_in[0];
    const int*   rt  = (const int*)d_in[1];
    const float* rw  = (const float*)d_in[2];
    const float* w13 = (const float*)d_in[3];
    const float* w2  = (const float*)d_in[4];
    float* out = (float*)d_out;

    cudaFuncSetAttribute(k_gemm1, cudaFuncAttributeMaxDynamicSharedMemorySize, SMEM_DYN);
    cudaFuncSetAttribute(k_gemm2, cudaFuncAttributeMaxDynamicSharedMemorySize, SMEM_DYN);

    const int n = T_TOK * H_DIM;
    k_clear<<<(n + 255) / 256, 256>>>(out, n);                       // my launch 0
    k_route<<<1, 256>>>(rt, rw);                                     // my launch 1
    k_splitall<<<11264, 256>>>(x, w13, w2);                          // my launch 2
    k_gemm1<<<dim3((2 * I_DIM) / 128, MAXT), 256, SMEM_DYN>>>();     // my launch 3 -> profiled
    k_gemm2<<<dim3(H_DIM / 128, MAXT), 256, SMEM_DYN>>>(out);        // my launch 4
}

// round 15
// speedup vs baseline: 1.3926x; 1.3926x over previous
#include <cuda_runtime.h>
#include <cuda_bf16.h>
#include <cstdint>

#define T_TOK   8192
#define H_DIM   2048
#define I_DIM   4096
#define NE      8
#define LISTCAP 16384
#define MAXT    160
#define HM_ROWS 17536

#define STG     16384          /* stage: Ah(4K)|Al(4K)|Bh(4K)|Bl(4K), 128 rows x 32B */
#define P_AL    4096
#define P_BH    8192
#define P_BL    12288

// ---------------- device scratch (no allocations allowed) ----------------
__device__ int   g_cnt[NE];
__device__ int   g_base[NE];
__device__ int   g_ntiles;
__device__ int   g_tile_e[MAXT];
__device__ int   g_tile_m[MAXT];
__device__ int   g_tok[NE * LISTCAP];
__device__ float g_coef[NE * LISTCAP];

__device__ __nv_bfloat16 g_xh[(size_t)T_TOK * H_DIM];
__device__ __nv_bfloat16 g_xl[(size_t)T_TOK * H_DIM];
__device__ __nv_bfloat16 g_w13h[(size_t)NE * 2 * I_DIM * H_DIM];   // permuted gate/up
__device__ __nv_bfloat16 g_w13l[(size_t)NE * 2 * I_DIM * H_DIM];
__device__ __nv_bfloat16 g_w2h[(size_t)NE * H_DIM * I_DIM];
__device__ __nv_bfloat16 g_w2l[(size_t)NE * H_DIM * I_DIM];
__device__ __nv_bfloat16 g_hmh[(size_t)HM_ROWS * I_DIM];
__device__ __nv_bfloat16 g_hml[(size_t)HM_ROWS * I_DIM];

// ---------------- helpers ----------------
__device__ __forceinline__ uint32_t smem_u32(const void* p) {
    uint32_t a;
    asm("{ .reg .u64 t; cvta.to.shared.u64 t, %1; cvt.u32.u64 %0, t; }" : "=r"(a) : "l"(p));
    return a;
}

// swizzled offset in a [128 rows][32B] plane: 16B chunk XOR'd with row bit2
#define SWZ16(r, c) ((uint32_t)((r) * 32 + ((((c) ^ (((r) >> 2) & 1))) << 4)))

#define CP16(dst, src) \
    asm volatile("cp.async.cg.shared.global [%0], [%1], 16;" :: "r"(dst), "l"(src))
#define CP_COMMIT() asm volatile("cp.async.commit_group;" ::: "memory")
#define CP_WAIT1()  asm volatile("cp.async.wait_group 1;" ::: "memory")
#define CP_WAIT0()  asm volatile("cp.async.wait_group 0;" ::: "memory")

__device__ __forceinline__ void ldsm4(uint32_t* r, uint32_t addr) {
    asm volatile("ldmatrix.sync.aligned.m8n8.x4.shared.b16 {%0,%1,%2,%3}, [%4];"
                 : "=r"(r[0]), "=r"(r[1]), "=r"(r[2]), "=r"(r[3]) : "r"(addr));
}

__device__ __forceinline__ void mma_bf16(float* c, const uint32_t* a,
                                         uint32_t b0, uint32_t b1) {
    asm volatile(
        "mma.sync.aligned.m16n8k16.row.col.f32.bf16.bf16.f32 "
        "{%0,%1,%2,%3}, {%4,%5,%6,%7}, {%8,%9}, {%0,%1,%2,%3};\n"
        : "+f"(c[0]), "+f"(c[1]), "+f"(c[2]), "+f"(c[3])
        : "r"(a[0]), "r"(a[1]), "r"(a[2]), "r"(a[3]), "r"(b0), "r"(b1));
}

__device__ __forceinline__ void split4(float4 v, uint2& hu, uint2& lu) {
    __nv_bfloat162 a, b, c, d;
    a.x = __float2bfloat16(v.x);
    a.y = __float2bfloat16(v.y);
    b.x = __float2bfloat16(v.z);
    b.y = __float2bfloat16(v.w);
    c.x = __float2bfloat16(v.x - __bfloat162float(a.x));
    c.y = __float2bfloat16(v.y - __bfloat162float(a.y));
    d.x = __float2bfloat16(v.z - __bfloat162float(b.x));
    d.y = __float2bfloat16(v.w - __bfloat162float(b.y));
    hu.x = *reinterpret_cast<unsigned*>(&a);
    hu.y = *reinterpret_cast<unsigned*>(&b);
    lu.x = *reinterpret_cast<unsigned*>(&c);
    lu.y = *reinterpret_cast<unsigned*>(&d);
}

__device__ __forceinline__ void srow(const float* __restrict__ src, int n4, int lane,
                                     __nv_bfloat16* dh, __nv_bfloat16* dl) {
    const float4* s4 = (const float4*)src;
    uint2* dh2 = (uint2*)dh;
    uint2* dl2 = (uint2*)dl;
    for (int i = lane; i < n4; i += 32) {
        uint2 hu, lu;
        split4(s4[i], hu, lu);
        dh2[i] = hu;
        dl2[i] = lu;
    }
}

// ---------------- small kernels ----------------
__global__ void k_clear(float* __restrict__ out, int n) {
    int i = blockIdx.x * 256 + threadIdx.x;
    if (i < n) out[i] = 0.0f;
}

__global__ void k_route(const int* __restrict__ rt, const float* __restrict__ rw) {
    __shared__ int scnt[NE], scur[NE];
    int tid = threadIdx.x;
    if (tid < NE) scnt[tid] = 0;
    __syncthreads();
    for (int t = tid; t < T_TOK; t += 256) {
        atomicAdd(&scnt[rt[2 * t]], 1);
        atomicAdd(&scnt[rt[2 * t + 1]], 1);
    }
    __syncthreads();
    if (tid == 0) {
        int base = 0, nt = 0;
        for (int e = 0; e < NE; ++e) {
            int c = scnt[e];
            g_cnt[e] = c;
            g_base[e] = base;
            for (int m0 = 0; m0 < c && nt < MAXT; m0 += 128) {
                g_tile_e[nt] = e;
                g_tile_m[nt] = m0;
                nt++;
            }
            base += (c + 127) / 128 * 128;
        }
        g_ntiles = nt;
    }
    if (tid < NE) scur[tid] = 0;
    __syncthreads();
    for (int t = tid; t < T_TOK; t += 256) {
#pragma unroll
        for (int k = 0; k < 2; ++k) {
            int e = rt[2 * t + k];
            int p = atomicAdd(&scur[e], 1);
            g_tok[e * LISTCAP + p]  = t;
            g_coef[e * LISTCAP + p] = rw[2 * t + k];
        }
    }
}

// splits X ([0,1024) blocks), permuted W13 ([1024,9216)), W2 ([9216,11264))
__global__ void k_splitall(const float* __restrict__ x, const float* __restrict__ w13,
                           const float* __restrict__ w2) {
    int wrow = blockIdx.x * 8 + (threadIdx.x >> 5);
    int lane = threadIdx.x & 31;
    if (blockIdx.x < 1024) {
        int row = wrow;
        srow(x + (size_t)row * H_DIM, H_DIM / 4, lane,
             g_xh + (size_t)row * H_DIM, g_xl + (size_t)row * H_DIM);
    } else if (blockIdx.x < 9216) {
        int row = wrow - 8192;
        int e = row >> 13, n = row & 8191;
        int j = n >> 1;
        int srcrow = (n & 1) ? (I_DIM + j) : j;
        srow(w13 + ((size_t)e * 2 * I_DIM + srcrow) * H_DIM, H_DIM / 4, lane,
             g_w13h + (size_t)row * H_DIM, g_w13l + (size_t)row * H_DIM);
    } else {
        int row = wrow - 73728;
        srow(w2 + (size_t)row * I_DIM, I_DIM / 4, lane,
             g_w2h + (size_t)row * I_DIM, g_w2l + (size_t)row * I_DIM);
    }
}

// ---------------- bf16 3-term fragment core (one K=16 stage) ----------------
// 4 warps: wm = wid&1 (64 rows of 128), wn = wid>>1 (64 cols of 128)
__device__ __forceinline__ void compute_stage(uint32_t st, int wm, int wn, int lane,
                                              float (&acc)[4][8][4]) {
    const int rsel = lane & 15;
    const int csel = lane >> 4;
    uint32_t bh[4][4], bl[4][4];
#pragma unroll
    for (int p = 0; p < 4; ++p) {
        uint32_t b = st + P_BH + SWZ16(wn * 64 + p * 16 + rsel, csel);
        ldsm4(bh[p], b);
        ldsm4(bl[p], b + (P_BL - P_BH));
    }
#pragma unroll
    for (int mf = 0; mf < 4; ++mf) {
        uint32_t ah[4], al[4];
        uint32_t a = st + SWZ16(wm * 64 + mf * 16 + rsel, csel);
        ldsm4(ah, a);
        ldsm4(al, a + P_AL);
#pragma unroll
        for (int p = 0; p < 4; ++p)
#pragma unroll
            for (int s = 0; s < 2; ++s) {
                int nf = p * 2 + s;
                mma_bf16(acc[mf][nf], ah, bh[p][s], bh[p][s + 2]);
                mma_bf16(acc[mf][nf], ah, bl[p][s], bl[p][s + 2]);
                mma_bf16(acc[mf][nf], al, bh[p][s], bh[p][s + 2]);
            }
    }
}

// ---------------- GEMM1: Xs[gathered 128] @ W13s^T[128], SwiGLU -> split Hm ------
__global__ __launch_bounds__(128, 2) void k_gemm1() {
    __shared__ __align__(128) char smem[3 * STG];

    const int tid = threadIdx.x, lane = tid & 31, wid = tid >> 5;
    const int wm = wid & 1, wn = wid >> 1;

    const int tile = blockIdx.y;
    if (tile >= g_ntiles) return;
    const int e   = g_tile_e[tile];
    const int m0  = g_tile_m[tile];
    const int n0  = blockIdx.x * 128;          // over 8192 permuted rows
    const int cnt = g_cnt[e];
    const int* tokp = g_tok + e * LISTCAP;

    // cp.async: thread t -> row t of all four planes, 2 chunks each (8 x 16B)
    const int r = tid;
    int tok = (m0 + r < cnt) ? tokp[m0 + r] : tokp[0];
    const __nv_bfloat16* ah_ = g_xh + (size_t)tok * H_DIM;
    const __nv_bfloat16* al_ = g_xl + (size_t)tok * H_DIM;
    const size_t brow = ((size_t)e * 2 * I_DIM + n0 + r) * H_DIM;
    const __nv_bfloat16* bh_ = g_w13h + brow;
    const __nv_bfloat16* bl_ = g_w13l + brow;

    const uint32_t sb = smem_u32(smem);
    const uint32_t d0 = SWZ16(r, 0);
    const uint32_t d1 = SWZ16(r, 1);

#define G_ISSUE(it)                                                          \
    do {                                                                     \
        uint32_t b_ = sb + ((it) % 3) * STG;                                 \
        int o_ = (it) * 16;                                                  \
        CP16(b_ + d0, ah_ + o_);                                             \
        CP16(b_ + d1, ah_ + o_ + 8);                                         \
        CP16(b_ + P_AL + d0, al_ + o_);                                      \
        CP16(b_ + P_AL + d1, al_ + o_ + 8);                                  \
        CP16(b_ + P_BH + d0, bh_ + o_);                                      \
        CP16(b_ + P_BH + d1, bh_ + o_ + 8);                                  \
        CP16(b_ + P_BL + d0, bl_ + o_);                                      \
        CP16(b_ + P_BL + d1, bl_ + o_ + 8);                                  \
        CP_COMMIT();                                                         \
    } while (0)

    float acc[4][8][4];
#pragma unroll
    for (int a = 0; a < 4; ++a)
#pragma unroll
        for (int b = 0; b < 8; ++b)
#pragma unroll
            for (int d = 0; d < 4; ++d) acc[a][b][d] = 0.0f;

    const int KT = H_DIM / 16;   // 128
    G_ISSUE(0);
    G_ISSUE(1);
#pragma unroll 1
    for (int it = 0; it < KT; ++it) {
        if (it < KT - 1) CP_WAIT1(); else CP_WAIT0();
        __syncthreads();
        if (it + 2 < KT) G_ISSUE(it + 2);
        compute_stage(sb + (it % 3) * STG, wm, wn, lane, acc);
        __syncthreads();
    }

    // epilogue: SwiGLU -> split bf16 Hm (gate even / up odd interleave)
    const int gq = lane >> 2, t4 = lane & 3;
    const int rowbase = g_base[e] + m0 + wm * 64;
#pragma unroll
    for (int mf = 0; mf < 4; ++mf) {
#pragma unroll
        for (int nf = 0; nf < 8; ++nf) {
            int j = ((n0 + wn * 64 + nf * 8) >> 1) + t4;
#pragma unroll
            for (int hh = 0; hh < 2; ++hh) {
                float g = acc[mf][nf][2 * hh];
                float u = acc[mf][nf][2 * hh + 1];
                float hv = u * g / (1.0f + __expf(-g));
                int row = rowbase + mf * 16 + gq + 8 * hh;
                __nv_bfloat16 hi = __float2bfloat16(hv);
                __nv_bfloat16 lo = __float2bfloat16(hv - __bfloat162float(hi));
                g_hmh[(size_t)row * I_DIM + j] = hi;
                g_hml[(size_t)row * I_DIM + j] = lo;
            }
        }
    }
#undef G_ISSUE
}

// ---------------- GEMM2: Hms[128] @ W2s^T[128], coef atomic scatter -> out ------
__global__ __launch_bounds__(128, 2) void k_gemm2(float* __restrict__ out) {
    __shared__ __align__(128) char smem[3 * STG];

    const int tid = threadIdx.x, lane = tid & 31, wid = tid >> 5;
    const int wm = wid & 1, wn = wid >> 1;

    const int tile = blockIdx.y;
    if (tile >= g_ntiles) return;
    const int e   = g_tile_e[tile];
    const int m0  = g_tile_m[tile];
    const int n0  = blockIdx.x * 128;          // over H_DIM
    const int cnt = g_cnt[e];
    const int rb  = g_base[e];

    const int r = tid;
    const size_t arow = (size_t)(rb + m0 + r) * I_DIM;
    const __nv_bfloat16* ah_ = g_hmh + arow;
    const __nv_bfloat16* al_ = g_hml + arow;
    const size_t brow = ((size_t)e * H_DIM + n0 + r) * I_DIM;
    const __nv_bfloat16* bh_ = g_w2h + brow;
    const __nv_bfloat16* bl_ = g_w2l + brow;

    const uint32_t sb = smem_u32(smem);
    const uint32_t d0 = SWZ16(r, 0);
    const uint32_t d1 = SWZ16(r, 1);

#define G_ISSUE(it)                                                          \
    do {                                                                     \
        uint32_t b_ = sb + ((it) % 3) * STG;                                 \
        int o_ = (it) * 16;                                                  \
        CP16(b_ + d0, ah_ + o_);                                             \
        CP16(b_ + d1, ah_ + o_ + 8);                                         \
        CP16(b_ + P_AL + d0, al_ + o_);                                      \
        CP16(b_ + P_AL + d1, al_ + o_ + 8);                                  \
        CP16(b_ + P_BH + d0, bh_ + o_);                                      \
        CP16(b_ + P_BH + d1, bh_ + o_ + 8);                                  \
        CP16(b_ + P_BL + d0, bl_ + o_);                                      \
        CP16(b_ + P_BL + d1, bl_ + o_ + 8);                                  \
        CP_COMMIT();                                                         \
    } while (0)

    float acc[4][8][4];
#pragma unroll
    for (int a = 0; a < 4; ++a)
#pragma unroll
        for (int b = 0; b < 8; ++b)
#pragma unroll
            for (int d = 0; d < 4; ++d) acc[a][b][d] = 0.0f;

    const int KT = I_DIM / 16;   // 256
    G_ISSUE(0);
    G_ISSUE(1);
#pragma unroll 1
    for (int it = 0; it < KT; ++it) {
        if (it < KT - 1) CP_WAIT1(); else CP_WAIT0();
        __syncthreads();
        if (it + 2 < KT) G_ISSUE(it + 2);
        compute_stage(sb + (it % 3) * STG, wm, wn, lane, acc);
        __syncthreads();
    }

    // epilogue: coef-scaled scatter (exactly 2 commutative fp32 adds / element)
    const int gq = lane >> 2, t4 = lane & 3;
    const int* tokp = g_tok + e * LISTCAP;
    const float* cfp = g_coef + e * LISTCAP;
#pragma unroll
    for (int mf = 0; mf < 4; ++mf) {
#pragma unroll
        for (int hh = 0; hh < 2; ++hh) {
            int mm = m0 + wm * 64 + mf * 16 + gq + 8 * hh;
            if (mm < cnt) {
                int tok  = tokp[mm];
                float cf = cfp[mm];
                float* orow = out + (size_t)tok * H_DIM;
#pragma unroll
                for (int nf = 0; nf < 8; ++nf) {
                    int col = n0 + wn * 64 + nf * 8 + 2 * t4;
                    atomicAdd(&orow[col],     cf * acc[mf][nf][2 * hh]);
                    atomicAdd(&orow[col + 1], cf * acc[mf][nf][2 * hh + 1]);
                }
            }
        }
    }
#undef G_ISSUE
}

// --------------------------------------------------------------------------
extern "C" void kernel_launch(void* const* d_in, const int* in_sizes, int n_in,
                              void* d_out, int out_size) {
    const float* x   = (const float*)d_in[0];
    const int*   rt  = (const int*)d_in[1];
    const float* rw  = (const float*)d_in[2];
    const float* w13 = (const float*)d_in[3];
    const float* w2  = (const float*)d_in[4];
    float* out = (float*)d_out;

    const int n = T_TOK * H_DIM;
    k_clear<<<(n + 255) / 256, 256>>>(out, n);                    // my launch 0
    k_route<<<1, 256>>>(rt, rw);                                  // my launch 1
    k_splitall<<<11264, 256>>>(x, w13, w2);                       // my launch 2
    k_gemm1<<<dim3((2 * I_DIM) / 128, MAXT), 128>>>();            // my launch 3 -> profiled
    k_gemm2<<<dim3(H_DIM / 128, MAXT), 128>>>(out);               // my launch 4
}

// round 16
// speedup vs baseline: 1.8637x; 1.3383x over previous
#include <cuda_runtime.h>
#include <cuda_bf16.h>
#include <cstdint>

#define T_TOK   8192
#define H_DIM   2048
#define I_DIM   4096
#define NE      8
#define LISTCAP 16384
#define MAXT    160
#define HM_ROWS 17536

// stage = KS=32: two k16 halves, each Ah|Al|Bh|Bl planes of 4KB (128 rows x 32B)
#define STG      32768
#define HALF     16384
#define P_AL     4096
#define P_BH     8192
#define P_BL     12288
#define SMEM_DYN (3 * STG)

// ---------------- device scratch (no allocations allowed) ----------------
__device__ int   g_cnt[NE];
__device__ int   g_base[NE];
__device__ int   g_ntiles;
__device__ int   g_tile_e[MAXT];
__device__ int   g_tile_m[MAXT];
__device__ int   g_tok[NE * LISTCAP];
__device__ float g_coef[NE * LISTCAP];

__device__ __nv_bfloat16 g_xh[(size_t)T_TOK * H_DIM];
__device__ __nv_bfloat16 g_xl[(size_t)T_TOK * H_DIM];
__device__ __nv_bfloat16 g_w13h[(size_t)NE * 2 * I_DIM * H_DIM];   // permuted gate/up
__device__ __nv_bfloat16 g_w13l[(size_t)NE * 2 * I_DIM * H_DIM];
__device__ __nv_bfloat16 g_w2h[(size_t)NE * H_DIM * I_DIM];
__device__ __nv_bfloat16 g_w2l[(size_t)NE * H_DIM * I_DIM];
__device__ __nv_bfloat16 g_hmh[(size_t)HM_ROWS * I_DIM];
__device__ __nv_bfloat16 g_hml[(size_t)HM_ROWS * I_DIM];

// ---------------- helpers ----------------
__device__ __forceinline__ uint32_t smem_u32(const void* p) {
    uint32_t a;
    asm("{ .reg .u64 t; cvta.to.shared.u64 t, %1; cvt.u32.u64 %0, t; }" : "=r"(a) : "l"(p));
    return a;
}

// swizzled offset in a [128 rows][32B] plane: 16B chunk XOR'd with row bit2
#define SWZ16(r, c) ((uint32_t)((r) * 32 + ((((c) ^ (((r) >> 2) & 1))) << 4)))

#define CP16(dst, src) \
    asm volatile("cp.async.cg.shared.global [%0], [%1], 16;" :: "r"(dst), "l"(src))
#define CP_COMMIT() asm volatile("cp.async.commit_group;" ::: "memory")
#define CP_WAIT1()  asm volatile("cp.async.wait_group 1;" ::: "memory")
#define CP_WAIT0()  asm volatile("cp.async.wait_group 0;" ::: "memory")

__device__ __forceinline__ void ldsm4(uint32_t* r, uint32_t addr) {
    asm volatile("ldmatrix.sync.aligned.m8n8.x4.shared.b16 {%0,%1,%2,%3}, [%4];"
                 : "=r"(r[0]), "=r"(r[1]), "=r"(r[2]), "=r"(r[3]) : "r"(addr));
}

__device__ __forceinline__ void mma_bf16(float* c, const uint32_t* a,
                                         uint32_t b0, uint32_t b1) {
    asm volatile(
        "mma.sync.aligned.m16n8k16.row.col.f32.bf16.bf16.f32 "
        "{%0,%1,%2,%3}, {%4,%5,%6,%7}, {%8,%9}, {%0,%1,%2,%3};\n"
        : "+f"(c[0]), "+f"(c[1]), "+f"(c[2]), "+f"(c[3])
        : "r"(a[0]), "r"(a[1]), "r"(a[2]), "r"(a[3]), "r"(b0), "r"(b1));
}

__device__ __forceinline__ void split4(float4 v, uint2& hu, uint2& lu) {
    __nv_bfloat162 a, b, c, d;
    a.x = __float2bfloat16(v.x);
    a.y = __float2bfloat16(v.y);
    b.x = __float2bfloat16(v.z);
    b.y = __float2bfloat16(v.w);
    c.x = __float2bfloat16(v.x - __bfloat162float(a.x));
    c.y = __float2bfloat16(v.y - __bfloat162float(a.y));
    d.x = __float2bfloat16(v.z - __bfloat162float(b.x));
    d.y = __float2bfloat16(v.w - __bfloat162float(b.y));
    hu.x = *reinterpret_cast<unsigned*>(&a);
    hu.y = *reinterpret_cast<unsigned*>(&b);
    lu.x = *reinterpret_cast<unsigned*>(&c);
    lu.y = *reinterpret_cast<unsigned*>(&d);
}

__device__ __forceinline__ void srow(const float* __restrict__ src, int n4, int lane,
                                     __nv_bfloat16* dh, __nv_bfloat16* dl) {
    const float4* s4 = (const float4*)src;
    uint2* dh2 = (uint2*)dh;
    uint2* dl2 = (uint2*)dl;
    for (int i = lane; i < n4; i += 32) {
        uint2 hu, lu;
        split4(s4[i], hu, lu);
        dh2[i] = hu;
        dl2[i] = lu;
    }
}

// ---------------- small kernels ----------------
__global__ void k_clear(float* __restrict__ out, int n) {
    int i = blockIdx.x * 256 + threadIdx.x;
    if (i < n) out[i] = 0.0f;
}

__global__ void k_route(const int* __restrict__ rt, const float* __restrict__ rw) {
    __shared__ int scnt[NE], scur[NE];
    int tid = threadIdx.x;
    if (tid < NE) scnt[tid] = 0;
    __syncthreads();
    for (int t = tid; t < T_TOK; t += 256) {
        atomicAdd(&scnt[rt[2 * t]], 1);
        atomicAdd(&scnt[rt[2 * t + 1]], 1);
    }
    __syncthreads();
    if (tid == 0) {
        int base = 0, nt = 0;
        for (int e = 0; e < NE; ++e) {
            int c = scnt[e];
            g_cnt[e] = c;
            g_base[e] = base;
            for (int m0 = 0; m0 < c && nt < MAXT; m0 += 128) {
                g_tile_e[nt] = e;
                g_tile_m[nt] = m0;
                nt++;
            }
            base += (c + 127) / 128 * 128;
        }
        g_ntiles = nt;
    }
    if (tid < NE) scur[tid] = 0;
    __syncthreads();
    for (int t = tid; t < T_TOK; t += 256) {
#pragma unroll
        for (int k = 0; k < 2; ++k) {
            int e = rt[2 * t + k];
            int p = atomicAdd(&scur[e], 1);
            g_tok[e * LISTCAP + p]  = t;
            g_coef[e * LISTCAP + p] = rw[2 * t + k];
        }
    }
}

// splits X ([0,1024) blocks), permuted W13 ([1024,9216)), W2 ([9216,11264))
__global__ void k_splitall(const float* __restrict__ x, const float* __restrict__ w13,
                           const float* __restrict__ w2) {
    int wrow = blockIdx.x * 8 + (threadIdx.x >> 5);
    int lane = threadIdx.x & 31;
    if (blockIdx.x < 1024) {
        int row = wrow;
        srow(x + (size_t)row * H_DIM, H_DIM / 4, lane,
             g_xh + (size_t)row * H_DIM, g_xl + (size_t)row * H_DIM);
    } else if (blockIdx.x < 9216) {
        int row = wrow - 8192;
        int e = row >> 13, n = row & 8191;
        int j = n >> 1;
        int srcrow = (n & 1) ? (I_DIM + j) : j;
        srow(w13 + ((size_t)e * 2 * I_DIM + srcrow) * H_DIM, H_DIM / 4, lane,
             g_w13h + (size_t)row * H_DIM, g_w13l + (size_t)row * H_DIM);
    } else {
        int row = wrow - 73728;
        srow(w2 + (size_t)row * I_DIM, I_DIM / 4, lane,
             g_w2h + (size_t)row * I_DIM, g_w2l + (size_t)row * I_DIM);
    }
}

// ---------------- bf16 3-term fragment core (one K=16 half) ----------------
// 8 warps: wm = wid&1 (64 rows of 128), wn = wid>>1 (32 cols of 128)
__device__ __forceinline__ void comp16(uint32_t st, int wm, int wn, int lane,
                                       float (&acc)[4][4][4]) {
    const int rsel = lane & 15;
    const int csel = lane >> 4;
    uint32_t bh[2][4], bl[2][4];
#pragma unroll
    for (int p = 0; p < 2; ++p) {
        uint32_t b = st + P_BH + SWZ16(wn * 32 + p * 16 + rsel, csel);
        ldsm4(bh[p], b);
        ldsm4(bl[p], b + (P_BL - P_BH));
    }
#pragma unroll
    for (int mf = 0; mf < 4; ++mf) {
        uint32_t ah[4], al[4];
        uint32_t a = st + SWZ16(wm * 64 + mf * 16 + rsel, csel);
        ldsm4(ah, a);
        ldsm4(al, a + P_AL);
#pragma unroll
        for (int p = 0; p < 2; ++p)
#pragma unroll
            for (int s = 0; s < 2; ++s) {
                int nf = p * 2 + s;
                mma_bf16(acc[mf][nf], ah, bh[p][s], bh[p][s + 2]);
                mma_bf16(acc[mf][nf], ah, bl[p][s], bl[p][s + 2]);
                mma_bf16(acc[mf][nf], al, bh[p][s], bh[p][s + 2]);
            }
    }
}

// ---------------- GEMM1: Xs[gathered 128] @ W13s^T[128], SwiGLU -> split Hm ------
__global__ __launch_bounds__(256, 2) void k_gemm1() {
    extern __shared__ __align__(128) char smem[];

    const int tid = threadIdx.x, lane = tid & 31, wid = tid >> 5;
    const int wm = wid & 1, wn = wid >> 1;

    const int tile = blockIdx.y;
    if (tile >= g_ntiles) return;
    const int e   = g_tile_e[tile];
    const int m0  = g_tile_m[tile];
    const int n0  = blockIdx.x * 128;          // over 8192 permuted rows
    const int cnt = g_cnt[e];
    const int* tokp = g_tok + e * LISTCAP;

    // cp.async: thread -> row r = tid>>1, chunk ct = tid&1; 8 x 16B per stage
    const int r = tid >> 1, ct = tid & 1;
    int tok = (m0 + r < cnt) ? tokp[m0 + r] : tokp[0];
    const __nv_bfloat16* ah_ = g_xh + (size_t)tok * H_DIM + ct * 8;
    const __nv_bfloat16* al_ = g_xl + (size_t)tok * H_DIM + ct * 8;
    const size_t brow = ((size_t)e * 2 * I_DIM + n0 + r) * H_DIM + ct * 8;
    const __nv_bfloat16* bh_ = g_w13h + brow;
    const __nv_bfloat16* bl_ = g_w13l + brow;

    const uint32_t sb = smem_u32(smem);
    const uint32_t d = SWZ16(r, ct);

#define G_ISSUE(it)                                                          \
    do {                                                                     \
        uint32_t b_ = sb + ((it) % 3) * STG;                                 \
        int o_ = (it) * 32;                                                  \
        CP16(b_ + d, ah_ + o_);                                              \
        CP16(b_ + HALF + d, ah_ + o_ + 16);                                  \
        CP16(b_ + P_AL + d, al_ + o_);                                       \
        CP16(b_ + HALF + P_AL + d, al_ + o_ + 16);                           \
        CP16(b_ + P_BH + d, bh_ + o_);                                       \
        CP16(b_ + HALF + P_BH + d, bh_ + o_ + 16);                           \
        CP16(b_ + P_BL + d, bl_ + o_);                                       \
        CP16(b_ + HALF + P_BL + d, bl_ + o_ + 16);                           \
        CP_COMMIT();                                                         \
    } while (0)

    float acc[4][4][4];
#pragma unroll
    for (int a = 0; a < 4; ++a)
#pragma unroll
        for (int b = 0; b < 4; ++b)
#pragma unroll
            for (int dd = 0; dd < 4; ++dd) acc[a][b][dd] = 0.0f;

    const int KT = H_DIM / 32;   // 64 stages of KS=32
    G_ISSUE(0);
    G_ISSUE(1);
#pragma unroll 1
    for (int it = 0; it < KT; ++it) {
        if (it < KT - 1) CP_WAIT1(); else CP_WAIT0();
        __syncthreads();
        if (it + 2 < KT) G_ISSUE(it + 2);
        uint32_t st = sb + (it % 3) * STG;
        comp16(st, wm, wn, lane, acc);
        comp16(st + HALF, wm, wn, lane, acc);
    }

    // epilogue: SwiGLU -> split bf16 Hm (gate even / up odd interleave)
    const int gq = lane >> 2, t4 = lane & 3;
    const int rowbase = g_base[e] + m0 + wm * 64;
#pragma unroll
    for (int mf = 0; mf < 4; ++mf) {
#pragma unroll
        for (int nf = 0; nf < 4; ++nf) {
            int pn = n0 + wn * 32 + nf * 8 + 2 * t4;
            int j = pn >> 1;
#pragma unroll
            for (int hh = 0; hh < 2; ++hh) {
                float g = acc[mf][nf][2 * hh];
                float u = acc[mf][nf][2 * hh + 1];
                float hv = u * g / (1.0f + __expf(-g));
                int row = rowbase + mf * 16 + gq + 8 * hh;
                __nv_bfloat16 hi = __float2bfloat16(hv);
                __nv_bfloat16 lo = __float2bfloat16(hv - __bfloat162float(hi));
                g_hmh[(size_t)row * I_DIM + j] = hi;
                g_hml[(size_t)row * I_DIM + j] = lo;
            }
        }
    }
#undef G_ISSUE
}

// ---------------- GEMM2: Hms[128] @ W2s^T[128], coef atomic scatter -> out ------
__global__ __launch_bounds__(256, 2) void k_gemm2(float* __restrict__ out) {
    extern __shared__ __align__(128) char smem[];

    const int tid = threadIdx.x, lane = tid & 31, wid = tid >> 5;
    const int wm = wid & 1, wn = wid >> 1;

    const int tile = blockIdx.y;
    if (tile >= g_ntiles) return;
    const int e   = g_tile_e[tile];
    const int m0  = g_tile_m[tile];
    const int n0  = blockIdx.x * 128;          // over H_DIM
    const int cnt = g_cnt[e];
    const int rb  = g_base[e];

    const int r = tid >> 1, ct = tid & 1;
    const size_t arow = (size_t)(rb + m0 + r) * I_DIM + ct * 8;
    const __nv_bfloat16* ah_ = g_hmh + arow;
    const __nv_bfloat16* al_ = g_hml + arow;
    const size_t brow = ((size_t)e * H_DIM + n0 + r) * I_DIM + ct * 8;
    const __nv_bfloat16* bh_ = g_w2h + brow;
    const __nv_bfloat16* bl_ = g_w2l + brow;

    const uint32_t sb = smem_u32(smem);
    const uint32_t d = SWZ16(r, ct);

#define G_ISSUE(it)                                                          \
    do {                                                                     \
        uint32_t b_ = sb + ((it) % 3) * STG;                                 \
        int o_ = (it) * 32;                                                  \
        CP16(b_ + d, ah_ + o_);                                              \
        CP16(b_ + HALF + d, ah_ + o_ + 16);                                  \
        CP16(b_ + P_AL + d, al_ + o_);                                       \
        CP16(b_ + HALF + P_AL + d, al_ + o_ + 16);                           \
        CP16(b_ + P_BH + d, bh_ + o_);                                       \
        CP16(b_ + HALF + P_BH + d, bh_ + o_ + 16);                           \
        CP16(b_ + P_BL + d, bl_ + o_);                                       \
        CP16(b_ + HALF + P_BL + d, bl_ + o_ + 16);                           \
        CP_COMMIT();                                                         \
    } while (0)

    float acc[4][4][4];
#pragma unroll
    for (int a = 0; a < 4; ++a)
#pragma unroll
        for (int b = 0; b < 4; ++b)
#pragma unroll
            for (int dd = 0; dd < 4; ++dd) acc[a][b][dd] = 0.0f;

    const int KT = I_DIM / 32;   // 128 stages of KS=32
    G_ISSUE(0);
    G_ISSUE(1);
#pragma unroll 1
    for (int it = 0; it < KT; ++it) {
        if (it < KT - 1) CP_WAIT1(); else CP_WAIT0();
        __syncthreads();
        if (it + 2 < KT) G_ISSUE(it + 2);
        uint32_t st = sb + (it % 3) * STG;
        comp16(st, wm, wn, lane, acc);
        comp16(st + HALF, wm, wn, lane, acc);
    }

    // epilogue: coef-scaled scatter (exactly 2 commutative fp32 adds / element)
    const int gq = lane >> 2, t4 = lane & 3;
    const int* tokp = g_tok + e * LISTCAP;
    const float* cfp = g_coef + e * LISTCAP;
#pragma unroll
    for (int mf = 0; mf < 4; ++mf) {
#pragma unroll
        for (int hh = 0; hh < 2; ++hh) {
            int mm = m0 + wm * 64 + mf * 16 + gq + 8 * hh;
            if (mm < cnt) {
                int tok  = tokp[mm];
                float cf = cfp[mm];
                float* orow = out + (size_t)tok * H_DIM;
#pragma unroll
                for (int nf = 0; nf < 4; ++nf) {
                    int col = n0 + wn * 32 + nf * 8 + 2 * t4;
                    atomicAdd(&orow[col],     cf * acc[mf][nf][2 * hh]);
                    atomicAdd(&orow[col + 1], cf * acc[mf][nf][2 * hh + 1]);
                }
            }
        }
    }
#undef G_ISSUE
}

// --------------------------------------------------------------------------
extern "C" void kernel_launch(void* const* d_in, const int* in_sizes, int n_in,
                              void* d_out, int out_size) {
    const float* x   = (const float*)d_in[0];
    const int*   rt  = (const int*)d_in[1];
    const float* rw  = (const float*)d_in[2];
    const float* w13 = (const float*)d_in[3];
    const float* w2  = (const float*)d_in[4];
    float* out = (float*)d_out;

    cudaFuncSetAttribute(k_gemm1, cudaFuncAttributeMaxDynamicSharedMemorySize, SMEM_DYN);
    cudaFuncSetAttribute(k_gemm2, cudaFuncAttributeMaxDynamicSharedMemorySize, SMEM_DYN);

    const int n = T_TOK * H_DIM;
    k_clear<<<(n + 255) / 256, 256>>>(out, n);                        // my launch 0
    k_route<<<1, 256>>>(rt, rw);                                      // my launch 1
    k_splitall<<<11264, 256>>>(x, w13, w2);                           // my launch 2
    k_gemm1<<<dim3((2 * I_DIM) / 128, MAXT), 256, SMEM_DYN>>>();      // my launch 3 -> profiled
    k_gemm2<<<dim3(H_DIM / 128, MAXT), 256, SMEM_DYN>>>(out);         // my launch 4
}